// round 6
// baseline (speedup 1.0000x reference)
#include <cuda_runtime.h>
#include <cuda_fp16.h>
#include <math.h>
#include <stdint.h>

#define NNODES 81920
#define NEDGES 1310720
#define NG     4096
#define NPG    20
#define IND    128
#define D      256
#define HIDC   64
#define NH     4
#define CAP    512            // per-graph edge capacity (mean 320, +10.7 sigma)
#define MAXE   (CAP + NPG)    // incl. self loops

// ---------------- scratch (no allocations allowed) ----------------
__device__ __align__(16) float g_h1lin[NNODES * D];   // gemm1 out; reused as xs after attn1
__device__ __align__(16) float g_h2lin[NNODES * D];
__device__ __align__(16) __half g_xhi[NNODES * IND];
__device__ __align__(16) __half g_xlo[NNODES * IND];
__device__ __align__(16) __half g_h1hi[NNODES * D];
__device__ __align__(16) __half g_h1lo[NNODES * D];
__device__ __align__(16) __half g_w1h[D * IND];
__device__ __align__(16) __half g_w2h[D * D];
__device__ __align__(16) float g_WhT[D * HIDC];
__device__ int g_cur[NG];
__device__ unsigned short g_epack[NG * CAP];

// ================= helpers =================
__device__ __forceinline__ uint32_t cvta_smem(const void* p) {
    uint32_t a;
    asm("{ .reg .u64 t; cvta.to.shared.u64 t, %1; cvt.u32.u64 %0, t; }" : "=r"(a) : "l"(p));
    return a;
}
__device__ __forceinline__ void cp16(uint32_t dst, const void* src) {
    asm volatile("cp.async.cg.shared.global [%0], [%1], 16;" :: "r"(dst), "l"(src) : "memory");
}
__device__ __forceinline__ void mma_f16(float* d, const uint32_t* a, uint32_t b0, uint32_t b1) {
    asm volatile(
        "mma.sync.aligned.m16n8k16.row.col.f32.f16.f16.f32 "
        "{%0,%1,%2,%3}, {%4,%5,%6,%7}, {%8,%9}, {%0,%1,%2,%3};"
        : "+f"(d[0]), "+f"(d[1]), "+f"(d[2]), "+f"(d[3])
        : "r"(a[0]), "r"(a[1]), "r"(a[2]), "r"(a[3]), "r"(b0), "r"(b1));
}
__device__ __forceinline__ void atomicMaxF(float* a, float v) {
    if (v >= 0.f) atomicMax((int*)a, __float_as_int(v));
    else atomicMin((unsigned int*)a, __float_as_uint(v));
}
__device__ __forceinline__ float lrelu(float v) { return (v >= 0.f) ? v : 0.2f * v; }

// ---------------- edge scatter (g_cur must be 0 on entry; attn2a resets it) ----------------
__global__ void k_scatter(const int* __restrict__ ei) {
    int e = blockIdx.x * blockDim.x + threadIdx.x;
    if (e < NEDGES) {
        int s = ei[e];
        int d = ei[NEDGES + e];
        int g = d / NPG;
        int p = atomicAdd(&g_cur[g], 1);
        if (p < CAP)
            g_epack[g * CAP + p] = (unsigned short)(((s - g * NPG) << 5) | (d - g * NPG));
    }
}

// ---------------- fused: x -> fp16 hi/lo split  +  W1 -> fp16 ----------------
#define N4X (NNODES * IND / 4)
#define N4W1 (D * IND / 4)
__global__ void k_prep1(const float* __restrict__ x, const float* __restrict__ W1) {
    int i = blockIdx.x * blockDim.x + threadIdx.x;
    if (i < N4X) {
        float4 v = ((const float4*)x)[i];
        __half h[4], l[4];
        float vv[4] = {v.x, v.y, v.z, v.w};
        #pragma unroll
        for (int j = 0; j < 4; j++) {
            h[j] = __float2half(vv[j]);
            l[j] = __float2half(vv[j] - __half2float(h[j]));
        }
        ((uint2*)g_xhi)[i] = *(uint2*)h;
        ((uint2*)g_xlo)[i] = *(uint2*)l;
    } else if (i < N4X + N4W1) {
        int j = i - N4X;
        float4 v = ((const float4*)W1)[j];
        __half h[4] = {__float2half(v.x), __float2half(v.y),
                       __float2half(v.z), __float2half(v.w)};
        ((uint2*)g_w1h)[j] = *(uint2*)h;
    }
}

// ---------------- fused: W2 -> fp16  +  Wh transpose ----------------
#define N4W2 (D * D / 4)
__global__ void k_prep2(const float* __restrict__ W2, const float* __restrict__ Wh) {
    int i = blockIdx.x * blockDim.x + threadIdx.x;
    if (i < N4W2) {
        float4 v = ((const float4*)W2)[i];
        __half h[4] = {__float2half(v.x), __float2half(v.y),
                       __float2half(v.z), __float2half(v.w)};
        ((uint2*)g_w2h)[i] = *(uint2*)h;
    } else if (i < N4W2 + D * HIDC) {
        int j = i - N4W2;           // j = k*64 + jc
        int k = j >> 6, jc = j & 63;
        g_WhT[j] = Wh[jc * D + k];
    }
}

// ============ fp16x2 mma.sync GEMM: C[M,256] = (Ahi+Alo)[M,K] * Bh[256,K]^T ============
#define ROWB 80
#define HALF_TILE (128 * ROWB)
#define STAGE_BYTES (3 * HALF_TILE)
#define GEMM_SMEM 69632

template <int K>
__global__ __launch_bounds__(256, 2)
void k_gemm_mma(const __half* __restrict__ Ahi, const __half* __restrict__ Alo,
                const __half* __restrict__ Bh, float* __restrict__ C) {
    extern __shared__ __align__(128) char smem[];
    const int tid = threadIdx.x;
    const int lane = tid & 31, wid = tid >> 5;
    const int warpm = wid & 3, warpn = wid >> 2;
    const int m0 = blockIdx.x * 128, n0 = blockIdx.y * 128;
    const uint32_t sb = cvta_smem(smem);
    const int NSTAGE = K / 32;

    float acc[2][8][4];
    #pragma unroll
    for (int i = 0; i < 2; i++)
        #pragma unroll
        for (int j = 0; j < 8; j++)
            #pragma unroll
            for (int q = 0; q < 4; q++) acc[i][j][q] = 0.f;

    auto prefetch = [&](int s) {
        uint32_t base = sb + (uint32_t)(s & 1) * STAGE_BYTES;
        #pragma unroll
        for (int l = 0; l < 2; l++) {
            int u = tid + l * 256;
            int row = u >> 2, ku = u & 3;
            uint32_t doff = (uint32_t)(row * ROWB + ku * 16);
            size_t goA = (size_t)(m0 + row) * K + s * 32 + ku * 8;
            size_t goB = (size_t)(n0 + row) * K + s * 32 + ku * 8;
            cp16(base + doff,                 Ahi + goA);
            cp16(base + HALF_TILE + doff,     Alo + goA);
            cp16(base + 2 * HALF_TILE + doff, Bh + goB);
        }
        asm volatile("cp.async.commit_group;" ::: "memory");
    };

    prefetch(0);
    #pragma unroll 1
    for (int s = 0; s < NSTAGE; s++) {
        if (s + 1 < NSTAGE) {
            prefetch(s + 1);
            asm volatile("cp.async.wait_group 1;" ::: "memory");
        } else {
            asm volatile("cp.async.wait_group 0;" ::: "memory");
        }
        __syncthreads();

        const char* base = smem + (s & 1) * STAGE_BYTES;
        const char* pAhi = base;
        const char* pAlo = base + HALF_TILE;
        const char* pB   = base + 2 * HALF_TILE;

        #pragma unroll
        for (int ks = 0; ks < 2; ks++) {
            const int kb = ks * 32 + (lane & 3) * 4;
            uint32_t ahi[2][4], alo[2][4];
            #pragma unroll
            for (int i = 0; i < 2; i++) {
                int r = warpm * 32 + i * 16 + (lane >> 2);
                int off = r * ROWB + kb;
                ahi[i][0] = *(const uint32_t*)(pAhi + off);
                ahi[i][1] = *(const uint32_t*)(pAhi + off + 8 * ROWB);
                ahi[i][2] = *(const uint32_t*)(pAhi + off + 16);
                ahi[i][3] = *(const uint32_t*)(pAhi + off + 8 * ROWB + 16);
                alo[i][0] = *(const uint32_t*)(pAlo + off);
                alo[i][1] = *(const uint32_t*)(pAlo + off + 8 * ROWB);
                alo[i][2] = *(const uint32_t*)(pAlo + off + 16);
                alo[i][3] = *(const uint32_t*)(pAlo + off + 8 * ROWB + 16);
            }
            #pragma unroll
            for (int j = 0; j < 8; j++) {
                int n = warpn * 64 + j * 8 + (lane >> 2);
                int off = n * ROWB + kb;
                uint32_t b0 = *(const uint32_t*)(pB + off);
                uint32_t b1 = *(const uint32_t*)(pB + off + 16);
                #pragma unroll
                for (int i = 0; i < 2; i++) {
                    mma_f16(acc[i][j], ahi[i], b0, b1);
                    mma_f16(acc[i][j], alo[i], b0, b1);
                }
            }
        }
        __syncthreads();
    }

    float* stg = (float*)smem;   // [128][132]
    #pragma unroll
    for (int i = 0; i < 2; i++) {
        int r = warpm * 32 + i * 16 + (lane >> 2);
        #pragma unroll
        for (int j = 0; j < 8; j++) {
            int c = warpn * 64 + j * 8 + (lane & 3) * 2;
            stg[r * 132 + c]           = acc[i][j][0];
            stg[r * 132 + c + 1]       = acc[i][j][1];
            stg[(r + 8) * 132 + c]     = acc[i][j][2];
            stg[(r + 8) * 132 + c + 1] = acc[i][j][3];
        }
    }
    __syncthreads();
    #pragma unroll
    for (int l = 0; l < 16; l++) {
        int f = tid + l * 256;
        int row = f >> 5, c4 = f & 31;
        *(float4*)&C[(size_t)(m0 + row) * D + n0 + c4 * 4] = *(float4*)&stg[row * 132 + c4 * 4];
    }
}

// ---------------- layer-1 attention: dense per-graph attention matrix ----------------
// Thread c keeps h[src][c] in registers; edges collapse into Wm[h][dst][src].
__global__ __launch_bounds__(256)
void k_attn1(const float* __restrict__ asrc, const float* __restrict__ adst,
             const float* __restrict__ bias) {
    __shared__ float hsh[NPG][260];                 // natural layout, conflict-free stores
    __shared__ __align__(16) float ssrc[NPG][NH];
    __shared__ __align__(16) float sdst[NPG][NH];
    __shared__ float ash[D], adsh[D], bsh[D];
    __shared__ float Wm[NH][NPG][NPG];              // dense exp-weight matrix
    __shared__ __align__(16) float mxs[NPG][NH];
    __shared__ __align__(16) float dnm[NPG][NH];
    __shared__ __align__(16) float alph[MAXE][NH];  // cached lrelu scores
    __shared__ unsigned short esh[MAXE];
    __shared__ int s_nE;

    const int g = blockIdx.x;
    const int tid = threadIdx.x;
    const int base = g * NPG;
    const int c = tid, h = c >> 6;

    // phase 0: features -> registers + natural SMEM copy; params; init
    float r[NPG];
    const float* hp = g_h1lin + (size_t)base * D;
    #pragma unroll
    for (int s = 0; s < NPG; s++) {
        r[s] = hp[s * D + c];
        hsh[s][c] = r[s];
    }
    ash[c] = asrc[c]; adsh[c] = adst[c]; bsh[c] = bias[c];
    for (int i = tid; i < NH * NPG * NPG; i += 256) ((float*)Wm)[i] = 0.f;
    if (tid < NPG * NH) ((float*)mxs)[tid] = -1e30f;

    int cnt = g_cur[g];
    if (cnt > CAP) cnt = CAP;
    for (int j = tid; j < cnt; j += 256) esh[j] = g_epack[g * CAP + j];
    if (tid < NPG) esh[cnt + tid] = (unsigned short)((tid << 5) | tid);  // self loops
    if (tid == 0) s_nE = cnt + NPG;
    __syncthreads();
    const int nE = s_nE;

    // phase 1: per-node scores (160 threads)
    if (tid < 2 * NPG * NH) {
        int t = tid;
        int which = t >= NPG * NH;
        t -= which * NPG * NH;
        int i = t >> 2, hh = t & 3;
        const float* av = which ? &adsh[hh * HIDC] : &ash[hh * HIDC];
        float s = 0.f;
        #pragma unroll 8
        for (int k = 0; k < HIDC; k++) s += hsh[i][hh * HIDC + k] * av[k];
        if (which) sdst[i][hh] = s; else ssrc[i][hh] = s;
    }
    __syncthreads();

    // phase 2 (pass A): lrelu scores + running max
    for (int j = tid; j < nE; j += 256) {
        unsigned short ev = esh[j];
        int dl = ev & 31, sl = ev >> 5;
        float4 s4 = *(const float4*)ssrc[sl];
        float4 d4 = *(const float4*)sdst[dl];
        float v0 = lrelu(s4.x + d4.x), v1 = lrelu(s4.y + d4.y);
        float v2 = lrelu(s4.z + d4.z), v3 = lrelu(s4.w + d4.w);
        *(float4*)alph[j] = make_float4(v0, v1, v2, v3);
        atomicMaxF(&mxs[dl][0], v0);
        atomicMaxF(&mxs[dl][1], v1);
        atomicMaxF(&mxs[dl][2], v2);
        atomicMaxF(&mxs[dl][3], v3);
    }
    __syncthreads();

    // phase 3 (pass B): exp + accumulate into dense Wm
    for (int j = tid; j < nE; j += 256) {
        unsigned short ev = esh[j];
        int dl = ev & 31, sl = ev >> 5;
        float4 a4 = *(const float4*)alph[j];
        float4 m4 = *(const float4*)mxs[dl];
        atomicAdd(&Wm[0][dl][sl], __expf(a4.x - m4.x));
        atomicAdd(&Wm[1][dl][sl], __expf(a4.y - m4.y));
        atomicAdd(&Wm[2][dl][sl], __expf(a4.z - m4.z));
        atomicAdd(&Wm[3][dl][sl], __expf(a4.w - m4.w));
    }
    __syncthreads();

    // phase 4: denominators (80 threads)
    if (tid < NPG * NH) {
        int dI = tid >> 2, hh = tid & 3;
        float sum = 0.f;
        #pragma unroll
        for (int s = 0; s < NPG; s++) sum += Wm[hh][dI][s];
        dnm[dI][hh] = 1.f / (sum + 1e-16f);
    }
    __syncthreads();

    // phase 5: dense aggregation from registers (broadcast-only LDS)
    float acc[NPG];
    #pragma unroll
    for (int d = 0; d < NPG; d++) acc[d] = 0.f;
    #pragma unroll 4
    for (int s = 0; s < NPG; s++) {
        float rv = r[s];
        #pragma unroll
        for (int d = 0; d < NPG; d++) acc[d] += Wm[h][d][s] * rv;
    }
    const float bv = bsh[c];
    __half* ohp = g_h1hi + (size_t)base * D + c;
    __half* olp = g_h1lo + (size_t)base * D + c;
    #pragma unroll
    for (int d = 0; d < NPG; d++) {
        float v = acc[d] * dnm[d][h] + bv;
        v = (v > 0.f) ? v : expm1f(v);
        __half hv = __float2half(v);
        ohp[d * D] = hv;
        olp[d * D] = __float2half(v - __half2float(hv));
    }
}

// ---------------- layer-2 attention at super node -> xs[G,256]; resets g_cur ----------------
__global__ __launch_bounds__(256)
void k_attn2a(const float* __restrict__ asrc, const float* __restrict__ adst,
              const float* __restrict__ bias2, float* __restrict__ xs) {
    __shared__ float hsh[NPG][D];
    __shared__ float ssrc[NPG][NH];
    __shared__ float sd19[NH];
    __shared__ float ash[NH * HIDC], adsh[NH * HIDC];
    __shared__ float b2sh[D];
    __shared__ unsigned short l19[192];
    __shared__ int s_n19;
    __shared__ float al19[192 * NH];

    const int g = blockIdx.x;
    const int tid = threadIdx.x;
    const int base = g * NPG;

    const float* hp = g_h2lin + (size_t)base * D;
    for (int i = tid; i < NPG * D / 4; i += 256)
        ((float4*)&hsh[0][0])[i] = ((const float4*)hp)[i];
    for (int i = tid; i < NH * HIDC; i += 256) { ash[i] = asrc[i]; adsh[i] = adst[i]; }
    for (int i = tid; i < D; i += 256) b2sh[i] = bias2[i];
    if (tid == 0) s_n19 = 0;
    __syncthreads();

    int off = g * CAP;
    int cnt = g_cur[g];
    if (cnt > CAP) cnt = CAP;
    for (int j = tid; j < cnt; j += 256) {
        unsigned short ev = g_epack[off + j];
        if ((ev & 31) == 19) {
            int p = atomicAdd(&s_n19, 1);
            if (p < 191) l19[p] = ev >> 5;
        }
    }
    if (tid < NPG * NH) {
        int i = tid >> 2, h = tid & 3;
        float s = 0.f;
        #pragma unroll 8
        for (int c = 0; c < HIDC; c++) s += hsh[i][h * HIDC + c] * ash[h * HIDC + c];
        ssrc[i][h] = s;
    } else if (tid < NPG * NH + NH) {
        int h = tid - NPG * NH;
        float s = 0.f;
        #pragma unroll 8
        for (int c = 0; c < HIDC; c++) s += hsh[19][h * HIDC + c] * adsh[h * HIDC + c];
        sd19[h] = s;
    }
    __syncthreads();
    if (tid == 0) {
        int m = s_n19 < 191 ? s_n19 : 191;
        l19[m] = 19;
        s_n19 = m + 1;
        g_cur[g] = 0;                  // reset for next invocation's scatter
    }
    __syncthreads();
    const int ne = s_n19;

    if (tid < NH) {
        int h = tid;
        float sd = sd19[h];
        float mx = -1e30f;
        for (int p = 0; p < ne; p++) {
            float v = ssrc[l19[p]][h] + sd;
            v = (v >= 0.f) ? v : 0.2f * v;
            al19[p * NH + h] = v;
            mx = fmaxf(mx, v);
        }
        float sum = 0.f;
        for (int p = 0; p < ne; p++) {
            float ex = expf(al19[p * NH + h] - mx);
            al19[p * NH + h] = ex;
            sum += ex;
        }
        float r = 1.f / (sum + 1e-16f);
        for (int p = 0; p < ne; p++) al19[p * NH + h] *= r;
    }
    __syncthreads();
    {
        int c = tid, h = c >> 6;
        float acc = 0.f;
        for (int p = 0; p < ne; p++)
            acc += al19[p * NH + h] * hsh[l19[p]][c];
        float v = acc + b2sh[c];
        xs[(size_t)g * D + c] = (v > 0.f) ? v : expm1f(v);
    }
}

// ---------------- MLP head: warp per graph, coalesced WhT ----------------
__global__ __launch_bounds__(256)
void k_head(const float* __restrict__ xs, const float* __restrict__ bh,
            const float* __restrict__ Wc, const float* __restrict__ bc,
            float* __restrict__ out) {
    __shared__ float xss[8][256];
    const int wid = threadIdx.x >> 5, lane = threadIdx.x & 31;
    const int g = blockIdx.x * 8 + wid;

    const float4* xr = (const float4*)(xs + (size_t)g * D);
    #pragma unroll
    for (int l = 0; l < 2; l++)
        ((float4*)xss[wid])[lane + l * 32] = xr[lane + l * 32];
    __syncwarp();

    float h0 = 0.f, h1 = 0.f;
    const int j0 = lane, j1 = 32 + lane;
    #pragma unroll 8
    for (int k = 0; k < D; k++) {
        float xv = xss[wid][k];
        h0 += xv * g_WhT[k * HIDC + j0];
        h1 += xv * g_WhT[k * HIDC + j1];
    }
    h0 += bh[j0]; h1 += bh[j1];
    h0 = (h0 > 0.f) ? h0 : 0.f;
    h1 = (h1 > 0.f) ? h1 : 0.f;
    float s = h0 * Wc[j0] + h1 * Wc[j1];
    #pragma unroll
    for (int o = 16; o; o >>= 1) s += __shfl_xor_sync(0xffffffffu, s, o);
    if (lane == 0) out[g] = s + bc[0];
}

// ---------------- launcher ----------------
extern "C" void kernel_launch(void* const* d_in, const int* in_sizes, int n_in,
                              void* d_out, int out_size) {
    const float* x   = (const float*)d_in[0];
    const int*   ei  = (const int*)d_in[1];
    const float* W1  = (const float*)d_in[3];
    const float* a1s = (const float*)d_in[4];
    const float* a1d = (const float*)d_in[5];
    const float* b1  = (const float*)d_in[6];
    const float* W2  = (const float*)d_in[7];
    const float* a2s = (const float*)d_in[8];
    const float* a2d = (const float*)d_in[9];
    const float* b2  = (const float*)d_in[10];
    const float* Wh  = (const float*)d_in[11];
    const float* bh  = (const float*)d_in[12];
    const float* Wc  = (const float*)d_in[13];
    const float* bc  = (const float*)d_in[14];
    float* out = (float*)d_out;

    void *p_h1lin, *p_h2lin, *p_xhi, *p_xlo, *p_h1hi, *p_h1lo, *p_w1h, *p_w2h;
    cudaGetSymbolAddress(&p_h1lin, g_h1lin);
    cudaGetSymbolAddress(&p_h2lin, g_h2lin);
    cudaGetSymbolAddress(&p_xhi, g_xhi);
    cudaGetSymbolAddress(&p_xlo, g_xlo);
    cudaGetSymbolAddress(&p_h1hi, g_h1hi);
    cudaGetSymbolAddress(&p_h1lo, g_h1lo);
    cudaGetSymbolAddress(&p_w1h, g_w1h);
    cudaGetSymbolAddress(&p_w2h, g_w2h);

    cudaFuncSetAttribute(k_gemm_mma<IND>, cudaFuncAttributeMaxDynamicSharedMemorySize, GEMM_SMEM);
    cudaFuncSetAttribute(k_gemm_mma<D>,   cudaFuncAttributeMaxDynamicSharedMemorySize, GEMM_SMEM);

    // idx0: scatter (g_cur zeroed by previous attn2a / static init)
    k_scatter<<<(NEDGES + 255) / 256, 256>>>(ei);
    // idx1: fused x split + W1 cvt
    k_prep1<<<(N4X + N4W1 + 255) / 256, 256>>>(x, W1);
    // idx2: gemm1
    k_gemm_mma<IND><<<dim3(NNODES / 128, 2), 256, GEMM_SMEM>>>(
        (const __half*)p_xhi, (const __half*)p_xlo, (const __half*)p_w1h, (float*)p_h1lin);
    // idx3: attn1 (profiled)
    k_attn1<<<NG, 256>>>(a1s, a1d, b1);
    // idx4: W2 cvt + Wh transpose
    k_prep2<<<(N4W2 + D * HIDC + 255) / 256, 256>>>(W2, Wh);
    // idx5: gemm2
    k_gemm_mma<D><<<dim3(NNODES / 128, 2), 256, GEMM_SMEM>>>(
        (const __half*)p_h1hi, (const __half*)p_h1lo, (const __half*)p_w2h, (float*)p_h2lin);
    // idx6: attn2 -> xs (reuses g_h1lin), resets g_cur
    k_attn2a<<<NG, 256>>>(a2s, a2d, b2, (float*)p_h1lin);
    // idx7: MLP head
    k_head<<<NG / 8, 256>>>((const float*)p_h1lin, bh, Wc, bc, out);
}